// round 1
// baseline (speedup 1.0000x reference)
#include <cuda_runtime.h>
#include <math.h>

#define NN 4096
#define EE 131072
#define CC 64
#define TT 32
#define SSC 5
#define LL 2
#define HRR 64
#define SHH 16
#define EPSF 1e-9f

// ---------------- device scratch (no runtime allocation allowed) ----------------
__device__ int    g_cnt[NN];
__device__ int    g_cur[NN];
__device__ int    g_off[NN + 1];
__device__ int    g_ss[EE];          // sorted send
__device__ int    g_sr[EE];          // sorted recv
__device__ float  g_hs[NN * CC];     // layer-0 node scalars
__device__ float  g_nf[NN * CC * SHH]; // node feats after layer 0
__device__ float4 g_Y[4 * EE];       // Y SoA by float4 group: [g*EE + e]
__device__ float  g_R[CC * EE];      // R SoA: [c*EE + e]
__device__ float  g_pos1[NN * 3];    // positions after layer 0
__device__ float  g_WmixT[LL * 4 * CC * CC];  // [l][i][d][c]
__device__ float  g_WprodT[LL * CC * CC];     // [l][d][c]

// ---------------- counting sort of edges by recv ----------------
__global__ void k_zero() {
    int i = blockIdx.x * 256 + threadIdx.x;
    if (i < NN) g_cnt[i] = 0;
    else if (i < 2 * NN) g_cur[i - NN] = 0;
}

__global__ void k_hist(const int* __restrict__ ei) {
    int e = blockIdx.x * 256 + threadIdx.x;
    atomicAdd(&g_cnt[ei[EE + e]], 1);
}

__global__ void k_scan() {
    __shared__ int sh[1024];
    int t = threadIdx.x;
    int4 v = ((const int4*)g_cnt)[t];
    int s = v.x + v.y + v.z + v.w;
    sh[t] = s;
    __syncthreads();
    for (int off = 1; off < 1024; off <<= 1) {
        int add = (t >= off) ? sh[t - off] : 0;
        __syncthreads();
        sh[t] += add;
        __syncthreads();
    }
    int excl = (t == 0) ? 0 : sh[t - 1];
    g_off[4 * t + 0] = excl;
    g_off[4 * t + 1] = excl + v.x;
    g_off[4 * t + 2] = excl + v.x + v.y;
    g_off[4 * t + 3] = excl + v.x + v.y + v.z;
    if (t == 1023) g_off[NN] = sh[1023];
}

__global__ void k_scatter(const int* __restrict__ ei) {
    int e = blockIdx.x * 256 + threadIdx.x;
    int s = ei[e];
    int r = ei[EE + e];
    int p = g_off[r] + atomicAdd(&g_cur[r], 1);
    g_ss[p] = s;
    g_sr[p] = r;
}

// ---------------- node embedding ----------------
__global__ void k_embed(const int* __restrict__ attrs,
                        const float* __restrict__ timeE,
                        const float* __restrict__ eW,
                        const float* __restrict__ eB) {
    int t = threadIdx.x;
    int n = blockIdx.x * 4 + (t >> 6);
    int c = t & 63;
    int a = attrs[n] - 1;
    float v = eB[c] + eW[a * CC + c];
    const float* tb = timeE + n * TT;
#pragma unroll
    for (int k = 0; k < TT; k++) v += tb[k] * eW[(SSC + k) * CC + c];
    g_hs[n * CC + c] = v;
}

// ---------------- weight transposes ----------------
__global__ void k_wprep(const float* __restrict__ Wmix,
                        const float* __restrict__ Wprod) {
    int tid = blockIdx.x * 256 + threadIdx.x;
    if (tid < LL * 4 * CC * CC) {
        int c = tid & 63;
        int d = (tid >> 6) & 63;
        int li = tid >> 12;  // l*4+i
        g_WmixT[tid] = Wmix[(li * CC + c) * CC + d];
    } else {
        int j = tid - LL * 4 * CC * CC;
        if (j < LL * CC * CC) {
            int c = j & 63;
            int d = (j >> 6) & 63;
            int l = j >> 12;
            g_WprodT[j] = Wprod[(l * CC + c) * CC + d];
        }
    }
}

// ---------------- per-edge: Y (sh16) + radial MLP R ----------------
template <int LAYER>
__global__ void __launch_bounds__(256) k_edge(const float* __restrict__ pos0,
                                              const float* __restrict__ W1,
                                              const float* __restrict__ B1,
                                              const float* __restrict__ W2) {
    int e = blockIdx.x * 256 + threadIdx.x;
    int s = g_ss[e];
    int r = g_sr[e];
    float p0sx = pos0[s * 3 + 0], p0sy = pos0[s * 3 + 1], p0sz = pos0[s * 3 + 2];
    float p0rx = pos0[r * 3 + 0], p0ry = pos0[r * 3 + 1], p0rz = pos0[r * 3 + 2];
    float vx, vy, vz, len, len0;
    if (LAYER == 0) {
        vx = p0rx - p0sx; vy = p0ry - p0sy; vz = p0rz - p0sz;
        len = sqrtf(vx * vx + vy * vy + vz * vz);
        len0 = len;
    } else {
        float psx = g_pos1[s * 3 + 0], psy = g_pos1[s * 3 + 1], psz = g_pos1[s * 3 + 2];
        float prx = g_pos1[r * 3 + 0], pry = g_pos1[r * 3 + 1], prz = g_pos1[r * 3 + 2];
        vx = prx - psx; vy = pry - psy; vz = prz - psz;
        len = sqrtf(vx * vx + vy * vy + vz * vz);
        float dx = p0rx - p0sx, dy = p0ry - p0sy, dz = p0rz - p0sz;
        len0 = sqrtf(dx * dx + dy * dy + dz * dz);
    }
    float inv = 1.0f / (len + EPSF);
    float x = vx * inv, y = vy * inv, z = vz * inv;

    // spherical harmonics l=0..3 ("component" normalization)
    float xx = x * x, yy = y * y, zz = z * z;
    float Y0 = 1.0f;
    float Y1 = 1.7320508075688772f * x;
    float Y2 = 1.7320508075688772f * y;
    float Y3 = 1.7320508075688772f * z;
    float Y4 = 3.872983346207417f * x * y;
    float Y5 = 3.872983346207417f * y * z;
    float Y6 = 1.118033988749895f * (3.0f * zz - 1.0f);
    float Y7 = 3.872983346207417f * x * z;
    float Y8 = 1.9364916731037085f * (xx - yy);
    float Y9 = 2.091650066335189f * y * (3.0f * xx - yy);
    float Y10 = 10.246950765959598f * x * y * z;
    float Y11 = 1.6201851746019651f * y * (5.0f * zz - 1.0f);
    float Y12 = 1.3228756555322954f * z * (5.0f * zz - 3.0f);
    float Y13 = 1.6201851746019651f * x * (5.0f * zz - 1.0f);
    float Y14 = 5.123475382979799f * z * (xx - yy);
    float Y15 = 2.091650066335189f * x * (xx - 3.0f * yy);
    g_Y[0 * EE + e] = make_float4(Y0, Y1, Y2, Y3);
    g_Y[1 * EE + e] = make_float4(Y4, Y5, Y6, Y7);
    g_Y[2 * EE + e] = make_float4(Y8, Y9, Y10, Y11);
    g_Y[3 * EE + e] = make_float4(Y12, Y13, Y14, Y15);

    // radial MLP: R = silu(rin @ W1 + b1) @ W2
    const float* w1a = W1 + LAYER * 2 * HRR;
    const float* w1b = w1a + HRR;
    const float* bb = B1 + LAYER * HRR;
    const float* w2 = W2 + LAYER * HRR * CC;

    float4 racc[16];
#pragma unroll
    for (int cg = 0; cg < 16; cg++) racc[cg] = make_float4(0.f, 0.f, 0.f, 0.f);

    for (int j = 0; j < HRR; j++) {
        float a = len0 * __ldg(&w1a[j]) + len * __ldg(&w1b[j]) + __ldg(&bb[j]);
        float hj = __fdividef(a, 1.0f + __expf(-a));
#pragma unroll
        for (int cg = 0; cg < 16; cg++) {
            float4 w = *(const float4*)&w2[j * CC + cg * 4];
            racc[cg].x += hj * w.x;
            racc[cg].y += hj * w.y;
            racc[cg].z += hj * w.z;
            racc[cg].w += hj * w.w;
        }
    }
#pragma unroll
    for (int cg = 0; cg < 16; cg++) {
        g_R[(4 * cg + 0) * EE + e] = racc[cg].x;
        g_R[(4 * cg + 1) * EE + e] = racc[cg].y;
        g_R[(4 * cg + 2) * EE + e] = racc[cg].z;
        g_R[(4 * cg + 3) * EE + e] = racc[cg].w;
    }
}

// ---------------- per-node: aggregate + mix + gate + prod + pos ----------------
template <int LAYER>
__global__ void __launch_bounds__(256) k_node(const float* __restrict__ pos_in,
                                              const float* __restrict__ pos0,
                                              const float* __restrict__ Wvec,
                                              float* __restrict__ pos_out) {
    constexpr bool LAST = (LAYER == LL - 1);
    int n = blockIdx.x;
    int t = threadIdx.x;
    int c = t >> 2;
    int xg = t & 3;
    int lane = t & 31;

    __shared__ __align__(16) float sA[16][64];
    __shared__ __align__(16) float sB[16][64];
    __shared__ float sG[64];

    float4 acc = make_float4(0.f, 0.f, 0.f, 0.f);
    int e0 = g_off[n], e1 = g_off[n + 1];
#pragma unroll 2
    for (int e = e0; e < e1; ++e) {
        int s = g_ss[e];
        float Rc = g_R[c * EE + e];
        float4 Y4 = g_Y[xg * EE + e];
        if (LAYER == 0) {
            float hs = g_hs[s * CC + c];
            float w = Rc * hs;
            acc.x += w * Y4.x; acc.y += w * Y4.y; acc.z += w * Y4.z; acc.w += w * Y4.w;
            if (xg == 0) acc.x += Rc * hs;  // tp term (only x=0 nonzero, Y0=1)
        } else {
            float4 h4 = *(const float4*)&g_nf[(s * CC + c) * SHH + xg * 4];
            float h0 = __shfl_sync(0xffffffffu, h4.x, lane & ~3);
            float w = Rc * h0;
            acc.x += w * Y4.x; acc.y += w * Y4.y; acc.z += w * Y4.z; acc.w += w * Y4.w;
            float tp = h4.x * Y4.x + h4.y * Y4.y + h4.z * Y4.z + h4.w * Y4.w;
            tp += __shfl_xor_sync(0xffffffffu, tp, 1);
            tp += __shfl_xor_sync(0xffffffffu, tp, 2);
            if (xg == 0) acc.x += Rc * tp;
        }
    }
    const float invAvg = 1.0f / 32.0f;
    acc.x *= invAvg; acc.y *= invAvg; acc.z *= invAvg; acc.w *= invAvg;

    // stage agg x-major: sA[x][c]
    sA[xg * 4 + 0][c] = acc.x;
    sA[xg * 4 + 1][c] = acc.y;
    sA[xg * 4 + 2][c] = acc.z;
    sA[xg * 4 + 3][c] = acc.w;
    __syncthreads();

    // mixing: mixed[d][x] = sum_c agg[c][x] * WmixT[l][i(x)][d][c]
    int d = c;
    const float* wbase[4];
#pragma unroll
    for (int k = 0; k < 4; k++) {
        int x = xg * 4 + k;
        int ib = (x == 0) ? 0 : (x < 4) ? 1 : (x < 9) ? 2 : 3;
        wbase[k] = &g_WmixT[(((LAYER * 4 + ib) * CC) + d) * CC];
    }
    float4 m4 = make_float4(0.f, 0.f, 0.f, 0.f);
    for (int cb = 0; cb < CC; cb += 4) {
#pragma unroll
        for (int k = 0; k < 4; k++) {
            float4 a4 = *(const float4*)&sA[xg * 4 + k][cb];
            float4 w4 = *(const float4*)&wbase[k][cb];
            (&m4.x)[k] += a4.x * w4.x + a4.y * w4.y + a4.z * w4.z + a4.w * w4.w;
        }
    }

    // stage mixed x-major: sB[x][d]
    sB[xg * 4 + 0][d] = m4.x;
    sB[xg * 4 + 1][d] = m4.y;
    sB[xg * 4 + 2][d] = m4.z;
    sB[xg * 4 + 3][d] = m4.w;
    __syncthreads();

    // gate[c] = s + s^2 + s^3
    if (t < 64) {
        float s0 = sB[0][t];
        sG[t] = s0 * (1.0f + s0 + s0 * s0);
    }
    __syncthreads();

    // sA <- mixed * gate (x-major)
#pragma unroll
    for (int k = 0; k < 4; k++) {
        int x = xg * 4 + k;
        sA[x][c] = sB[x][c] * sG[c];
    }
    __syncthreads();

    // prod: nf[d][x] = mixed[d][x] + sum_c (mixed[c][x]*gate[c]) * WprodT[l][d][c]
    float4 p4 = make_float4(0.f, 0.f, 0.f, 0.f);
    const float* wp = &g_WprodT[(LAYER * CC + d) * CC];
    for (int cb = 0; cb < CC; cb += 4) {
        float4 w4 = *(const float4*)&wp[cb];
#pragma unroll
        for (int k = 0; k < 4; k++) {
            float4 g4 = *(const float4*)&sA[xg * 4 + k][cb];
            (&p4.x)[k] += g4.x * w4.x + g4.y * w4.y + g4.z * w4.z + g4.w * w4.w;
        }
    }
    float4 nf4;
    nf4.x = m4.x + p4.x; nf4.y = m4.y + p4.y; nf4.z = m4.z + p4.z; nf4.w = m4.w + p4.w;
    if (!LAST) {
        *(float4*)&g_nf[(n * CC + d) * SHH + xg * 4] = nf4;
    }

    // mbv[j] = sum_d nf[d][1+j] * Wvec[d]  (x=1,2,3 live in xg==0 threads)
    if (xg == 0) {
        float wv = Wvec[d];
        sB[0][d] = nf4.y * wv;
        sB[1][d] = nf4.z * wv;
        sB[2][d] = nf4.w * wv;
    }
    __syncthreads();
    if (t < 3) {
        float sum = 0.f;
#pragma unroll 8
        for (int dd = 0; dd < 64; dd++) sum += sB[t][dd];
        float p = pos_in[n * 3 + t] + sum;
        if (LAST) pos_out[n * 3 + t] = p - pos0[n * 3 + t];
        else pos_out[n * 3 + t] = p;
    }
}

// ---------------- launch ----------------
extern "C" void kernel_launch(void* const* d_in, const int* in_sizes, int n_in,
                              void* d_out, int out_size) {
    const float* positions = (const float*)d_in[0];
    const int*   node_attrs = (const int*)d_in[1];
    const float* time_emb = (const float*)d_in[2];
    const int*   edge_index = (const int*)d_in[3];
    const float* embed_W = (const float*)d_in[4];
    const float* embed_b = (const float*)d_in[5];
    const float* radial_W1 = (const float*)d_in[6];
    const float* radial_b1 = (const float*)d_in[7];
    const float* radial_W2 = (const float*)d_in[8];
    const float* Wmix = (const float*)d_in[9];
    const float* Wprod = (const float*)d_in[10];
    const float* Wvec = (const float*)d_in[11];
    float* out = (float*)d_out;

    float* g_pos1_p = nullptr;
    cudaGetSymbolAddress((void**)&g_pos1_p, g_pos1);

    k_zero<<<(2 * NN + 255) / 256, 256>>>();
    k_hist<<<EE / 256, 256>>>(edge_index);
    k_scan<<<1, 1024>>>();
    k_scatter<<<EE / 256, 256>>>(edge_index);
    k_embed<<<NN / 4, 256>>>(node_attrs, time_emb, embed_W, embed_b);
    k_wprep<<<(LL * 4 * CC * CC + LL * CC * CC + 255) / 256, 256>>>(Wmix, Wprod);

    // layer 0
    k_edge<0><<<EE / 256, 256>>>(positions, radial_W1, radial_b1, radial_W2);
    k_node<0><<<NN, 256>>>(positions, positions, Wvec + 0 * CC, g_pos1_p);
    // layer 1
    k_edge<1><<<EE / 256, 256>>>(positions, radial_W1, radial_b1, radial_W2);
    k_node<1><<<NN, 256>>>(g_pos1_p, positions, Wvec + 1 * CC, out);
}

// round 2
// speedup vs baseline: 1.1491x; 1.1491x over previous
#include <cuda_runtime.h>
#include <math.h>

#define NN 4096
#define EE 131072
#define CC 64
#define TT 32
#define SSC 5
#define LL 2
#define HRR 64
#define SHH 16
#define EPSF 1e-9f

// ---------------- device scratch (static, zero-initialized at load) ----------------
__device__ int    g_cnt[NN];         // zeroed by k_scan for next replay
__device__ int    g_cur[NN];         // zeroed by k_scan for this replay's scatter
__device__ int    g_off[NN + 1];
__device__ int    g_ss[EE];          // sorted send
__device__ int    g_sr[EE];          // sorted recv
__device__ float  g_hs[NN * CC];     // layer-0 node scalars
__device__ float  g_nf[NN * CC * SHH]; // node feats after layer 0
__device__ float4 g_Y[EE * 4];       // Y per edge: [e*4 + g]
__device__ float  g_R[EE * CC];      // R per edge (already /AVG): [e*CC + c]
__device__ float  g_pos1[NN * 3];    // positions after layer 0
__device__ float  g_WmixT[LL * 4 * CC * CC];  // [l][i][d][c]
__device__ float  g_WprodT[LL * CC * CC];     // [l][d][c]

// ---------------- counting sort of edges by recv ----------------
__global__ void k_hist(const int* __restrict__ ei) {
    int e = blockIdx.x * 256 + threadIdx.x;
    atomicAdd(&g_cnt[ei[EE + e]], 1);
}

__global__ void k_scan() {
    __shared__ int sh[1024];
    int t = threadIdx.x;
    int4 v = ((const int4*)g_cnt)[t];
    int s = v.x + v.y + v.z + v.w;
    sh[t] = s;
    __syncthreads();
    for (int off = 1; off < 1024; off <<= 1) {
        int add = (t >= off) ? sh[t - off] : 0;
        __syncthreads();
        sh[t] += add;
        __syncthreads();
    }
    int excl = (t == 0) ? 0 : sh[t - 1];
    g_off[4 * t + 0] = excl;
    g_off[4 * t + 1] = excl + v.x;
    g_off[4 * t + 2] = excl + v.x + v.y;
    g_off[4 * t + 3] = excl + v.x + v.y + v.z;
    if (t == 1023) g_off[NN] = sh[1023];
    // re-zero for next replay (cnt) and for this replay's scatter (cur)
    ((int4*)g_cnt)[t] = make_int4(0, 0, 0, 0);
    ((int4*)g_cur)[t] = make_int4(0, 0, 0, 0);
}

__global__ void k_scatter(const int* __restrict__ ei) {
    int e = blockIdx.x * 256 + threadIdx.x;
    int s = ei[e];
    int r = ei[EE + e];
    int p = g_off[r] + atomicAdd(&g_cur[r], 1);
    g_ss[p] = s;
    g_sr[p] = r;
}

// ---------------- fused embedding + weight transposes ----------------
__global__ void k_prep(const int* __restrict__ attrs,
                       const float* __restrict__ timeE,
                       const float* __restrict__ eW,
                       const float* __restrict__ eB,
                       const float* __restrict__ Wmix,
                       const float* __restrict__ Wprod) {
    int b = blockIdx.x;
    int t = threadIdx.x;
    if (b < 1024) {
        // embedding: 4 nodes per block
        int n = b * 4 + (t >> 6);
        int c = t & 63;
        int a = attrs[n] - 1;
        float v = eB[c] + eW[a * CC + c];
        const float* tb = timeE + n * TT;
#pragma unroll
        for (int k = 0; k < TT; k++) v += tb[k] * eW[(SSC + k) * CC + c];
        g_hs[n * CC + c] = v;
    } else {
        int tid = (b - 1024) * 256 + t;
        if (tid < LL * 4 * CC * CC) {
            int c = tid & 63;
            int d = (tid >> 6) & 63;
            int li = tid >> 12;  // l*4+i
            g_WmixT[tid] = Wmix[(li * CC + c) * CC + d];
        } else {
            int j = tid - LL * 4 * CC * CC;
            if (j < LL * CC * CC) {
                int c = j & 63;
                int d = (j >> 6) & 63;
                int l = j >> 12;
                g_WprodT[j] = Wprod[(l * CC + c) * CC + d];
            }
        }
    }
}

// ---------------- per-edge: Y (sh16) + radial MLP R ----------------
// 4 threads per edge; each thread produces 16 of the 64 R outputs.
// W2 staged in shared with a 4x4 float4-transpose so LDS.128 is conflict-free.
template <int LAYER>
__global__ void __launch_bounds__(256) k_edge(const float* __restrict__ pos0,
                                              const float* __restrict__ W1,
                                              const float* __restrict__ B1,
                                              const float* __restrict__ W2) {
    __shared__ __align__(16) float4 sW2[HRR * 16];  // [j*16 + (k*4+sub)]
    __shared__ float sW1a[HRR], sW1b[HRR], sBB[HRR];

    int t = threadIdx.x;
    const float* w2 = W2 + LAYER * HRR * CC;
    for (int i = t; i < HRR * 16; i += 256) {
        int j = i >> 4, cg = i & 15;
        int p = ((cg & 3) << 2) | (cg >> 2);  // transpose 4x4 grid of float4 slots
        sW2[j * 16 + p] = *(const float4*)&w2[j * CC + cg * 4];
    }
    if (t < HRR) {
        sW1a[t] = W1[LAYER * 2 * HRR + t];
        sW1b[t] = W1[LAYER * 2 * HRR + HRR + t];
        sBB[t] = B1[LAYER * HRR + t];
    }
    __syncthreads();

    int sub = t & 3;
    int e = blockIdx.x * 64 + (t >> 2);
    int s = g_ss[e];
    int r = g_sr[e];

    float p0sx = pos0[s * 3 + 0], p0sy = pos0[s * 3 + 1], p0sz = pos0[s * 3 + 2];
    float p0rx = pos0[r * 3 + 0], p0ry = pos0[r * 3 + 1], p0rz = pos0[r * 3 + 2];
    float vx, vy, vz, len, len0;
    if (LAYER == 0) {
        vx = p0rx - p0sx; vy = p0ry - p0sy; vz = p0rz - p0sz;
        len = sqrtf(vx * vx + vy * vy + vz * vz);
        len0 = len;
    } else {
        float psx = g_pos1[s * 3 + 0], psy = g_pos1[s * 3 + 1], psz = g_pos1[s * 3 + 2];
        float prx = g_pos1[r * 3 + 0], pry = g_pos1[r * 3 + 1], prz = g_pos1[r * 3 + 2];
        vx = prx - psx; vy = pry - psy; vz = prz - psz;
        len = sqrtf(vx * vx + vy * vy + vz * vz);
        float dx = p0rx - p0sx, dy = p0ry - p0sy, dz = p0rz - p0sz;
        len0 = sqrtf(dx * dx + dy * dy + dz * dz);
    }
    float inv = 1.0f / (len + EPSF);
    float x = vx * inv, y = vy * inv, z = vz * inv;

    // spherical harmonics l=0..3 ("component" normalization)
    float xx = x * x, yy = y * y, zz = z * z;
    float Yv[16];
    Yv[0] = 1.0f;
    Yv[1] = 1.7320508075688772f * x;
    Yv[2] = 1.7320508075688772f * y;
    Yv[3] = 1.7320508075688772f * z;
    Yv[4] = 3.872983346207417f * x * y;
    Yv[5] = 3.872983346207417f * y * z;
    Yv[6] = 1.118033988749895f * (3.0f * zz - 1.0f);
    Yv[7] = 3.872983346207417f * x * z;
    Yv[8] = 1.9364916731037085f * (xx - yy);
    Yv[9] = 2.091650066335189f * y * (3.0f * xx - yy);
    Yv[10] = 10.246950765959598f * x * y * z;
    Yv[11] = 1.6201851746019651f * y * (5.0f * zz - 1.0f);
    Yv[12] = 1.3228756555322954f * z * (5.0f * zz - 3.0f);
    Yv[13] = 1.6201851746019651f * x * (5.0f * zz - 1.0f);
    Yv[14] = 5.123475382979799f * z * (xx - yy);
    Yv[15] = 2.091650066335189f * x * (xx - 3.0f * yy);
    g_Y[e * 4 + sub] = make_float4(Yv[sub * 4 + 0], Yv[sub * 4 + 1],
                                   Yv[sub * 4 + 2], Yv[sub * 4 + 3]);

    // radial MLP: R = (1/AVG) * silu(rin @ W1 + b1) @ W2
    float4 racc[4];
#pragma unroll
    for (int k = 0; k < 4; k++) racc[k] = make_float4(0.f, 0.f, 0.f, 0.f);

    const float4* rowBase = &sW2[sub];
#pragma unroll 2
    for (int j = 0; j < HRR; j++) {
        float a = fmaf(len0, sW1a[j], fmaf(len, sW1b[j], sBB[j]));
        float hj = __fdividef(a, 1.0f + __expf(-a));
        const float4* row = rowBase + j * 16;
#pragma unroll
        for (int k = 0; k < 4; k++) {
            float4 w = row[k * 4];
            racc[k].x += hj * w.x;
            racc[k].y += hj * w.y;
            racc[k].z += hj * w.z;
            racc[k].w += hj * w.w;
        }
    }
    const float invAvg = 1.0f / 32.0f;
    float4* out = (float4*)&g_R[e * CC + sub * 16];
#pragma unroll
    for (int k = 0; k < 4; k++) {
        racc[k].x *= invAvg; racc[k].y *= invAvg; racc[k].z *= invAvg; racc[k].w *= invAvg;
        out[k] = racc[k];
    }
}

// ---------------- per-node: aggregate + mix + gate + prod + pos ----------------
template <int LAYER>
__global__ void __launch_bounds__(256) k_node(const float* __restrict__ pos_in,
                                              const float* __restrict__ pos0,
                                              const float* __restrict__ Wvec,
                                              float* __restrict__ pos_out) {
    constexpr bool LAST = (LAYER == LL - 1);
    int n = blockIdx.x;
    int t = threadIdx.x;
    int c = t >> 2;
    int xg = t & 3;
    int lane = t & 31;

    __shared__ __align__(16) float sA[16][64];
    __shared__ __align__(16) float sB[16][64];
    __shared__ float sG[64];

    float4 acc = make_float4(0.f, 0.f, 0.f, 0.f);
    int e0 = g_off[n], e1 = g_off[n + 1];
#pragma unroll 2
    for (int e = e0; e < e1; ++e) {
        int s = g_ss[e];
        float Rc = g_R[e * CC + c];          // already scaled by 1/AVG
        float4 Y4 = g_Y[e * 4 + xg];
        if (LAYER == 0) {
            float hs = g_hs[s * CC + c];
            float w = Rc * hs;
            acc.x += w * Y4.x; acc.y += w * Y4.y; acc.z += w * Y4.z; acc.w += w * Y4.w;
            if (xg == 0) acc.x += Rc * hs;  // tp term (only x=0 nonzero, Y0=1)
        } else {
            float4 h4 = *(const float4*)&g_nf[(s * CC + c) * SHH + xg * 4];
            float h0 = __shfl_sync(0xffffffffu, h4.x, lane & ~3);
            float w = Rc * h0;
            acc.x += w * Y4.x; acc.y += w * Y4.y; acc.z += w * Y4.z; acc.w += w * Y4.w;
            float tp = h4.x * Y4.x + h4.y * Y4.y + h4.z * Y4.z + h4.w * Y4.w;
            tp += __shfl_xor_sync(0xffffffffu, tp, 1);
            tp += __shfl_xor_sync(0xffffffffu, tp, 2);
            if (xg == 0) acc.x += Rc * tp;
        }
    }

    // stage agg x-major: sA[x][c]
    sA[xg * 4 + 0][c] = acc.x;
    sA[xg * 4 + 1][c] = acc.y;
    sA[xg * 4 + 2][c] = acc.z;
    sA[xg * 4 + 3][c] = acc.w;
    __syncthreads();

    // mixing: mixed[d][x] = sum_c agg[c][x] * WmixT[l][i(x)][d][c]
    int d = c;
    const float* wbase[4];
#pragma unroll
    for (int k = 0; k < 4; k++) {
        int xi = xg * 4 + k;
        int ib = (xi == 0) ? 0 : (xi < 4) ? 1 : (xi < 9) ? 2 : 3;
        wbase[k] = &g_WmixT[(((LAYER * 4 + ib) * CC) + d) * CC];
    }
    float4 m4 = make_float4(0.f, 0.f, 0.f, 0.f);
    for (int cb = 0; cb < CC; cb += 4) {
#pragma unroll
        for (int k = 0; k < 4; k++) {
            float4 a4 = *(const float4*)&sA[xg * 4 + k][cb];
            float4 w4 = *(const float4*)&wbase[k][cb];
            (&m4.x)[k] += a4.x * w4.x + a4.y * w4.y + a4.z * w4.z + a4.w * w4.w;
        }
    }

    // stage mixed x-major: sB[x][d]
    sB[xg * 4 + 0][d] = m4.x;
    sB[xg * 4 + 1][d] = m4.y;
    sB[xg * 4 + 2][d] = m4.z;
    sB[xg * 4 + 3][d] = m4.w;
    __syncthreads();

    // gate[c] = s + s^2 + s^3
    if (t < 64) {
        float s0 = sB[0][t];
        sG[t] = s0 * (1.0f + s0 + s0 * s0);
    }
    __syncthreads();

    // sA <- mixed * gate (x-major)
#pragma unroll
    for (int k = 0; k < 4; k++) {
        int xi = xg * 4 + k;
        sA[xi][c] = sB[xi][c] * sG[c];
    }
    __syncthreads();

    // prod: nf[d][x] = mixed[d][x] + sum_c (mixed[c][x]*gate[c]) * WprodT[l][d][c]
    float4 p4 = make_float4(0.f, 0.f, 0.f, 0.f);
    const float* wp = &g_WprodT[(LAYER * CC + d) * CC];
    for (int cb = 0; cb < CC; cb += 4) {
        float4 w4 = *(const float4*)&wp[cb];
#pragma unroll
        for (int k = 0; k < 4; k++) {
            float4 g4 = *(const float4*)&sA[xg * 4 + k][cb];
            (&p4.x)[k] += g4.x * w4.x + g4.y * w4.y + g4.z * w4.z + g4.w * w4.w;
        }
    }
    float4 nf4;
    nf4.x = m4.x + p4.x; nf4.y = m4.y + p4.y; nf4.z = m4.z + p4.z; nf4.w = m4.w + p4.w;
    if (!LAST) {
        *(float4*)&g_nf[(n * CC + d) * SHH + xg * 4] = nf4;
    }

    // mbv[j] = sum_d nf[d][1+j] * Wvec[d]  (x=1,2,3 live in xg==0 threads)
    if (xg == 0) {
        float wv = Wvec[d];
        sB[0][d] = nf4.y * wv;
        sB[1][d] = nf4.z * wv;
        sB[2][d] = nf4.w * wv;
    }
    __syncthreads();
    if (t < 3) {
        float sum = 0.f;
#pragma unroll 8
        for (int dd = 0; dd < 64; dd++) sum += sB[t][dd];
        float p = pos_in[n * 3 + t] + sum;
        if (LAST) pos_out[n * 3 + t] = p - pos0[n * 3 + t];
        else pos_out[n * 3 + t] = p;
    }
}

// ---------------- launch ----------------
extern "C" void kernel_launch(void* const* d_in, const int* in_sizes, int n_in,
                              void* d_out, int out_size) {
    const float* positions = (const float*)d_in[0];
    const int*   node_attrs = (const int*)d_in[1];
    const float* time_emb = (const float*)d_in[2];
    const int*   edge_index = (const int*)d_in[3];
    const float* embed_W = (const float*)d_in[4];
    const float* embed_b = (const float*)d_in[5];
    const float* radial_W1 = (const float*)d_in[6];
    const float* radial_b1 = (const float*)d_in[7];
    const float* radial_W2 = (const float*)d_in[8];
    const float* Wmix = (const float*)d_in[9];
    const float* Wprod = (const float*)d_in[10];
    const float* Wvec = (const float*)d_in[11];
    float* out = (float*)d_out;

    float* g_pos1_p = nullptr;
    cudaGetSymbolAddress((void**)&g_pos1_p, g_pos1);

    const int PREP_W = (LL * 4 * CC * CC + LL * CC * CC + 255) / 256;  // wprep blocks

    k_hist<<<EE / 256, 256>>>(edge_index);
    k_scan<<<1, 1024>>>();
    k_scatter<<<EE / 256, 256>>>(edge_index);
    // layer 0 edges (independent of embedding)
    k_edge<0><<<EE / 64, 256>>>(positions, radial_W1, radial_b1, radial_W2);
    // embedding + weight transposes (needed from node0 onward)
    k_prep<<<1024 + PREP_W, 256>>>(node_attrs, time_emb, embed_W, embed_b, Wmix, Wprod);
    k_node<0><<<NN, 256>>>(positions, positions, Wvec + 0 * CC, g_pos1_p);
    // layer 1
    k_edge<1><<<EE / 64, 256>>>(positions, radial_W1, radial_b1, radial_W2);
    k_node<1><<<NN, 256>>>(g_pos1_p, positions, Wvec + 1 * CC, out);
}

// round 3
// speedup vs baseline: 3.1288x; 2.7228x over previous
#include <cuda_runtime.h>
#include <math.h>

#define NN 4096
#define EE 131072
#define CC 64
#define TT 32
#define SSC 5
#define LL 2
#define HRR 64
#define SHH 16
#define EPSF 1e-9f

// ---------------- device scratch (static, zero-initialized at load) ----------------
__device__ int    g_cnt[NN];
__device__ int    g_cur[NN];
__device__ int    g_off[NN + 1];
__device__ int    g_ss[EE];            // sorted send
__device__ int    g_sr[EE];            // sorted recv
__device__ float  g_hs[NN * CC];       // layer-0 node scalars
__device__ float  g_nf[NN * SHH * CC]; // node feats after layer 0, [n][x][c]
__device__ float4 g_Y[EE * 4];         // Y per (sorted) edge: [e*4 + g]
__device__ float  g_R[EE * CC];        // R per (sorted) edge (already /AVG): [e*CC + c]
__device__ float  g_pos1[NN * 3];      // positions after layer 0

// ---------------- fused: histogram + node embedding ----------------
__global__ void k_hist_prep(const int* __restrict__ ei,
                            const int* __restrict__ attrs,
                            const float* __restrict__ timeE,
                            const float* __restrict__ eW,
                            const float* __restrict__ eB) {
    int b = blockIdx.x;
    int t = threadIdx.x;
    if (b < 512) {
        int e = b * 256 + t;
        atomicAdd(&g_cnt[ei[EE + e]], 1);
    } else {
        int n = (b - 512) * 4 + (t >> 6);
        int c = t & 63;
        int a = attrs[n] - 1;
        float v = eB[c] + eW[a * CC + c];
        const float* tb = timeE + n * TT;
#pragma unroll
        for (int k = 0; k < TT; k++) v += tb[k] * eW[(SSC + k) * CC + c];
        g_hs[n * CC + c] = v;
    }
}

// ---------------- scan (and re-zero counters) ----------------
__global__ void k_scan() {
    __shared__ int sh[1024];
    int t = threadIdx.x;
    int4 v = ((const int4*)g_cnt)[t];
    int s = v.x + v.y + v.z + v.w;
    sh[t] = s;
    __syncthreads();
    for (int off = 1; off < 1024; off <<= 1) {
        int add = (t >= off) ? sh[t - off] : 0;
        __syncthreads();
        sh[t] += add;
        __syncthreads();
    }
    int excl = (t == 0) ? 0 : sh[t - 1];
    g_off[4 * t + 0] = excl;
    g_off[4 * t + 1] = excl + v.x;
    g_off[4 * t + 2] = excl + v.x + v.y;
    g_off[4 * t + 3] = excl + v.x + v.y + v.z;
    if (t == 1023) g_off[NN] = sh[1023];
    ((int4*)g_cnt)[t] = make_int4(0, 0, 0, 0);   // for next replay
    ((int4*)g_cur)[t] = make_int4(0, 0, 0, 0);   // for this replay's scatter
}

// ---------------- shared edge math ----------------
__device__ __forceinline__ void sh16_quarter(float x, float y, float z, int sub, float4* out) {
    float xx = x * x, yy = y * y, zz = z * z;
    float Yv[16];
    Yv[0] = 1.0f;
    Yv[1] = 1.7320508075688772f * x;
    Yv[2] = 1.7320508075688772f * y;
    Yv[3] = 1.7320508075688772f * z;
    Yv[4] = 3.872983346207417f * x * y;
    Yv[5] = 3.872983346207417f * y * z;
    Yv[6] = 1.118033988749895f * (3.0f * zz - 1.0f);
    Yv[7] = 3.872983346207417f * x * z;
    Yv[8] = 1.9364916731037085f * (xx - yy);
    Yv[9] = 2.091650066335189f * y * (3.0f * xx - yy);
    Yv[10] = 10.246950765959598f * x * y * z;
    Yv[11] = 1.6201851746019651f * y * (5.0f * zz - 1.0f);
    Yv[12] = 1.3228756555322954f * z * (5.0f * zz - 3.0f);
    Yv[13] = 1.6201851746019651f * x * (5.0f * zz - 1.0f);
    Yv[14] = 5.123475382979799f * z * (xx - yy);
    Yv[15] = 2.091650066335189f * x * (xx - 3.0f * yy);
    *out = make_float4(Yv[sub * 4 + 0], Yv[sub * 4 + 1], Yv[sub * 4 + 2], Yv[sub * 4 + 3]);
}

__device__ __forceinline__ void radial_quarter(float len0, float len, int sub,
                                               const float4* __restrict__ sW2,
                                               const float* __restrict__ sW1a,
                                               const float* __restrict__ sW1b,
                                               const float* __restrict__ sBB,
                                               float4* racc) {
#pragma unroll
    for (int k = 0; k < 4; k++) racc[k] = make_float4(0.f, 0.f, 0.f, 0.f);
    const float4* rowBase = &sW2[sub];
#pragma unroll 2
    for (int j = 0; j < HRR; j++) {
        float a = fmaf(len0, sW1a[j], fmaf(len, sW1b[j], sBB[j]));
        float hj = __fdividef(a, 1.0f + __expf(-a));
        const float4* row = rowBase + j * 16;
#pragma unroll
        for (int k = 0; k < 4; k++) {
            float4 w = row[k * 4];
            racc[k].x += hj * w.x;
            racc[k].y += hj * w.y;
            racc[k].z += hj * w.z;
            racc[k].w += hj * w.w;
        }
    }
    const float invAvg = 1.0f / 32.0f;
#pragma unroll
    for (int k = 0; k < 4; k++) {
        racc[k].x *= invAvg; racc[k].y *= invAvg; racc[k].z *= invAvg; racc[k].w *= invAvg;
    }
}

// ---------------- fused: scatter + layer-0 edge (Y, R) ----------------
// 4 threads per edge; sub 0 claims the sorted slot p, broadcasts via shuffle.
__global__ void __launch_bounds__(256) k_scatter_edge0(const int* __restrict__ ei,
                                                       const float* __restrict__ pos,
                                                       const float* __restrict__ W1,
                                                       const float* __restrict__ B1,
                                                       const float* __restrict__ W2) {
    __shared__ __align__(16) float4 sW2[HRR * 16];
    __shared__ float sW1a[HRR], sW1b[HRR], sBB[HRR];
    int t = threadIdx.x;
    for (int i = t; i < HRR * 16; i += 256) {
        int j = i >> 4, cg = i & 15;
        int p = ((cg & 3) << 2) | (cg >> 2);
        sW2[j * 16 + p] = *(const float4*)&W2[j * CC + cg * 4];
    }
    if (t < HRR) {
        sW1a[t] = W1[t];
        sW1b[t] = W1[HRR + t];
        sBB[t] = B1[t];
    }
    __syncthreads();

    int sub = t & 3;
    int lane = t & 31;
    int e = blockIdx.x * 64 + (t >> 2);
    int s = ei[e];
    int r = ei[EE + e];

    int p = 0;
    if (sub == 0) {
        p = g_off[r] + atomicAdd(&g_cur[r], 1);
        g_ss[p] = s;
        g_sr[p] = r;
    }
    p = __shfl_sync(0xffffffffu, p, lane & ~3);

    float vx = pos[r * 3 + 0] - pos[s * 3 + 0];
    float vy = pos[r * 3 + 1] - pos[s * 3 + 1];
    float vz = pos[r * 3 + 2] - pos[s * 3 + 2];
    float len = sqrtf(vx * vx + vy * vy + vz * vz);
    float inv = 1.0f / (len + EPSF);

    float4 yq;
    sh16_quarter(vx * inv, vy * inv, vz * inv, sub, &yq);
    g_Y[p * 4 + sub] = yq;

    float4 racc[4];
    radial_quarter(len, len, sub, sW2, sW1a, sW1b, sBB, racc);
    float4* out = (float4*)&g_R[p * CC + sub * 16];
#pragma unroll
    for (int k = 0; k < 4; k++) out[k] = racc[k];
}

// ---------------- layer-1 edge (reads sorted edges + updated positions) ----------------
__global__ void __launch_bounds__(256) k_edge1(const float* __restrict__ pos0,
                                               const float* __restrict__ W1,
                                               const float* __restrict__ B1,
                                               const float* __restrict__ W2) {
    __shared__ __align__(16) float4 sW2[HRR * 16];
    __shared__ float sW1a[HRR], sW1b[HRR], sBB[HRR];
    int t = threadIdx.x;
    for (int i = t; i < HRR * 16; i += 256) {
        int j = i >> 4, cg = i & 15;
        int p = ((cg & 3) << 2) | (cg >> 2);
        sW2[j * 16 + p] = *(const float4*)&W2[HRR * CC + j * CC + cg * 4];
    }
    if (t < HRR) {
        sW1a[t] = W1[2 * HRR + t];
        sW1b[t] = W1[3 * HRR + t];
        sBB[t] = B1[HRR + t];
    }
    __syncthreads();

    int sub = t & 3;
    int e = blockIdx.x * 64 + (t >> 2);
    int s = g_ss[e];
    int r = g_sr[e];

    float vx = g_pos1[r * 3 + 0] - g_pos1[s * 3 + 0];
    float vy = g_pos1[r * 3 + 1] - g_pos1[s * 3 + 1];
    float vz = g_pos1[r * 3 + 2] - g_pos1[s * 3 + 2];
    float len = sqrtf(vx * vx + vy * vy + vz * vz);
    float dx = pos0[r * 3 + 0] - pos0[s * 3 + 0];
    float dy = pos0[r * 3 + 1] - pos0[s * 3 + 1];
    float dz = pos0[r * 3 + 2] - pos0[s * 3 + 2];
    float len0 = sqrtf(dx * dx + dy * dy + dz * dz);
    float inv = 1.0f / (len + EPSF);

    float4 yq;
    sh16_quarter(vx * inv, vy * inv, vz * inv, sub, &yq);
    g_Y[e * 4 + sub] = yq;

    float4 racc[4];
    radial_quarter(len0, len, sub, sW2, sW1a, sW1b, sBB, racc);
    float4* out = (float4*)&g_R[e * CC + sub * 16];
#pragma unroll
    for (int k = 0; k < 4; k++) out[k] = racc[k];
}

// ---------------- per-node: aggregate + mix + gate + prod + pos ----------------
// 128 threads = 2 nodes x 64 channels. No shuffles; all weight LDGs coalesced
// in the ORIGINAL Wmix/Wprod layouts (lane = output channel d).
template <int LAYER>
__global__ void __launch_bounds__(128) k_node(const float* __restrict__ pos_in,
                                              const float* __restrict__ pos0,
                                              const float* __restrict__ Wmix,
                                              const float* __restrict__ Wprod,
                                              const float* __restrict__ Wvec,
                                              float* __restrict__ pos_out) {
    constexpr bool LAST = (LAYER == LL - 1);
    int t = threadIdx.x;
    int ni = t >> 6;
    int d = t & 63;
    int n = blockIdx.x * 2 + ni;

    __shared__ __align__(16) float sS[2][64][16];
    __shared__ float sG[2][64];
    __shared__ float sV[2][3][64];

    float acc[16];
#pragma unroll
    for (int x = 0; x < 16; x++) acc[x] = 0.f;

    int e0 = g_off[n], e1 = g_off[n + 1];
#pragma unroll 2
    for (int e = e0; e < e1; ++e) {
        int s = g_ss[e];
        float R = g_R[e * CC + d];          // already /AVG
        const float4* Yp = &g_Y[e * 4];
        float4 Ya = Yp[0], Yb = Yp[1], Yc = Yp[2], Yd = Yp[3];
        float Yv[16] = {Ya.x, Ya.y, Ya.z, Ya.w, Yb.x, Yb.y, Yb.z, Yb.w,
                        Yc.x, Yc.y, Yc.z, Yc.w, Yd.x, Yd.y, Yd.z, Yd.w};
        if (LAYER == 0) {
            float hs = g_hs[s * CC + d];
            float w = R * hs;
            acc[0] += 2.0f * w;             // m (Y0=1) + tp
#pragma unroll
            for (int x = 1; x < 16; x++) acc[x] += w * Yv[x];
        } else {
            float hv[16];
#pragma unroll
            for (int x = 0; x < 16; x++) hv[x] = g_nf[(s * SHH + x) * CC + d];
            float w = R * hv[0];
            float tp = 0.f;
#pragma unroll
            for (int x = 0; x < 16; x++) tp += hv[x] * Yv[x];
            acc[0] += w + R * tp;
#pragma unroll
            for (int x = 1; x < 16; x++) acc[x] += w * Yv[x];
        }
    }

    // stage agg row-major: sS[ni][c][x]
    float4* st = (float4*)&sS[ni][d][0];
    st[0] = make_float4(acc[0], acc[1], acc[2], acc[3]);
    st[1] = make_float4(acc[4], acc[5], acc[6], acc[7]);
    st[2] = make_float4(acc[8], acc[9], acc[10], acc[11]);
    st[3] = make_float4(acc[12], acc[13], acc[14], acc[15]);
    __syncthreads();

    // mixing: mixed[d][x] = sum_cc agg[cc][x] * Wmix[l][ib(x)][cc][d]   (coalesced over d)
    float m[16];
#pragma unroll
    for (int x = 0; x < 16; x++) m[x] = 0.f;
    const float* Wm = Wmix + LAYER * 4 * CC * CC;
#pragma unroll 4
    for (int cc = 0; cc < CC; cc++) {
        float w0 = Wm[(0 * CC + cc) * CC + d];
        float w1 = Wm[(1 * CC + cc) * CC + d];
        float w2 = Wm[(2 * CC + cc) * CC + d];
        float w3 = Wm[(3 * CC + cc) * CC + d];
        const float4* ap = (const float4*)&sS[ni][cc][0];
        float4 a0 = ap[0], a1 = ap[1], a2 = ap[2], a3 = ap[3];
        m[0]  += a0.x * w0;
        m[1]  += a0.y * w1;  m[2]  += a0.z * w1;  m[3]  += a0.w * w1;
        m[4]  += a1.x * w2;  m[5]  += a1.y * w2;  m[6]  += a1.z * w2;  m[7] += a1.w * w2;
        m[8]  += a2.x * w2;
        m[9]  += a2.y * w3;  m[10] += a2.z * w3;  m[11] += a2.w * w3;
        m[12] += a3.x * w3;  m[13] += a3.y * w3;  m[14] += a3.z * w3;  m[15] += a3.w * w3;
    }
    __syncthreads();  // done reading agg

    // stage mixed + gate
    st[0] = make_float4(m[0], m[1], m[2], m[3]);
    st[1] = make_float4(m[4], m[5], m[6], m[7]);
    st[2] = make_float4(m[8], m[9], m[10], m[11]);
    st[3] = make_float4(m[12], m[13], m[14], m[15]);
    float s0 = m[0];
    sG[ni][d] = s0 * (1.0f + s0 + s0 * s0);
    __syncthreads();

    // prod: nf[d][x] = mixed[d][x] + sum_cc mixed[cc][x]*gate[cc]*Wprod[cc][d]  (coalesced over d)
    float pr[16];
#pragma unroll
    for (int x = 0; x < 16; x++) pr[x] = 0.f;
    const float* Wp = Wprod + LAYER * CC * CC;
#pragma unroll 4
    for (int cc = 0; cc < CC; cc++) {
        float wg = Wp[cc * CC + d] * sG[ni][cc];
        const float4* ap = (const float4*)&sS[ni][cc][0];
        float4 a0 = ap[0], a1 = ap[1], a2 = ap[2], a3 = ap[3];
        pr[0]  += a0.x * wg;  pr[1]  += a0.y * wg;  pr[2]  += a0.z * wg;  pr[3]  += a0.w * wg;
        pr[4]  += a1.x * wg;  pr[5]  += a1.y * wg;  pr[6]  += a1.z * wg;  pr[7]  += a1.w * wg;
        pr[8]  += a2.x * wg;  pr[9]  += a2.y * wg;  pr[10] += a2.z * wg;  pr[11] += a2.w * wg;
        pr[12] += a3.x * wg;  pr[13] += a3.y * wg;  pr[14] += a3.z * wg;  pr[15] += a3.w * wg;
    }
    float nf[16];
#pragma unroll
    for (int x = 0; x < 16; x++) nf[x] = m[x] + pr[x];

    if (!LAST) {
#pragma unroll
        for (int x = 0; x < 16; x++) g_nf[(n * SHH + x) * CC + d] = nf[x];
    }

    // mbv[j] = sum_d nf[d][1+j]*Wvec[d]
    float wv = Wvec[d];
    sV[ni][0][d] = nf[1] * wv;
    sV[ni][1][d] = nf[2] * wv;
    sV[ni][2][d] = nf[3] * wv;
    __syncthreads();
    if (d < 3) {
        float sum = 0.f;
#pragma unroll 8
        for (int dd = 0; dd < CC; dd++) sum += sV[ni][d][dd];
        float pp = pos_in[n * 3 + d] + sum;
        pos_out[n * 3 + d] = LAST ? (pp - pos0[n * 3 + d]) : pp;
    }
}

// ---------------- launch ----------------
extern "C" void kernel_launch(void* const* d_in, const int* in_sizes, int n_in,
                              void* d_out, int out_size) {
    const float* positions = (const float*)d_in[0];
    const int*   node_attrs = (const int*)d_in[1];
    const float* time_emb = (const float*)d_in[2];
    const int*   edge_index = (const int*)d_in[3];
    const float* embed_W = (const float*)d_in[4];
    const float* embed_b = (const float*)d_in[5];
    const float* radial_W1 = (const float*)d_in[6];
    const float* radial_b1 = (const float*)d_in[7];
    const float* radial_W2 = (const float*)d_in[8];
    const float* Wmix = (const float*)d_in[9];
    const float* Wprod = (const float*)d_in[10];
    const float* Wvec = (const float*)d_in[11];
    float* out = (float*)d_out;

    float* g_pos1_p = nullptr;
    cudaGetSymbolAddress((void**)&g_pos1_p, g_pos1);

    k_hist_prep<<<512 + 1024, 256>>>(edge_index, node_attrs, time_emb, embed_W, embed_b);
    k_scan<<<1, 1024>>>();
    k_scatter_edge0<<<EE / 64, 256>>>(edge_index, positions, radial_W1, radial_b1, radial_W2);
    k_node<0><<<NN / 2, 128>>>(positions, positions, Wmix, Wprod, Wvec + 0 * CC, g_pos1_p);
    k_edge1<<<EE / 64, 256>>>(positions, radial_W1, radial_b1, radial_W2);
    k_node<1><<<NN / 2, 128>>>(g_pos1_p, positions, Wmix, Wprod, Wvec + 1 * CC, out);
}

// round 4
// speedup vs baseline: 3.4957x; 1.1173x over previous
#include <cuda_runtime.h>
#include <math.h>

#define NN 4096
#define EE 131072
#define CC 64
#define TT 32
#define SSC 5
#define LL 2
#define HRR 64
#define SHH 16
#define EPSF 1e-9f
#define TE 256            // edges per edge-kernel block

typedef unsigned long long u64;

__device__ __forceinline__ u64 pk2(float a, float b) {
    u64 r; asm("mov.b64 %0,{%1,%2};" : "=l"(r) : "f"(a), "f"(b)); return r;
}
__device__ __forceinline__ u64 dup2(float a) { return pk2(a, a); }
__device__ __forceinline__ void upk2(u64 v, float& a, float& b) {
    asm("mov.b64 {%0,%1},%2;" : "=f"(a), "=f"(b) : "l"(v));
}
__device__ __forceinline__ void fma2(u64& d, u64 a, u64 b) {
    asm("fma.rn.f32x2 %0,%1,%2,%0;" : "+l"(d) : "l"(a), "l"(b));
}
__device__ __forceinline__ u64 add2(u64 a, u64 b) {
    u64 r; asm("add.rn.f32x2 %0,%1,%2;" : "=l"(r) : "l"(a), "l"(b)); return r;
}

// ---------------- device scratch (static, zero-initialized at load) ----------------
__device__ int    g_cnt[NN];
__device__ int    g_cur[NN];
__device__ int    g_off[NN + 1];
__device__ int    g_ss[EE];            // sorted send
__device__ int    g_sr[EE];            // sorted recv
__device__ float  g_hs[NN * CC];       // layer-0 node scalars
__device__ float  g_nf[NN * SHH * CC]; // node feats after layer 0, [n][x][c]
__device__ float4 g_Y[EE * 4];         // Y per sorted edge: [e*4 + g]
__device__ float  g_R[EE * CC];        // R per sorted edge (already /AVG): [e*CC + c]
__device__ float  g_pos1[NN * 3];      // positions after layer 0

// ---------------- fused: histogram + node embedding ----------------
__global__ void k_hist_prep(const int* __restrict__ ei,
                            const int* __restrict__ attrs,
                            const float* __restrict__ timeE,
                            const float* __restrict__ eW,
                            const float* __restrict__ eB) {
    int b = blockIdx.x;
    int t = threadIdx.x;
    if (b < 512) {
        int e = b * 256 + t;
        atomicAdd(&g_cnt[ei[EE + e]], 1);
    } else {
        int n = (b - 512) * 4 + (t >> 6);
        int c = t & 63;
        int a = attrs[n] - 1;
        float v = eB[c] + eW[a * CC + c];
        const float* tb = timeE + n * TT;
#pragma unroll
        for (int k = 0; k < TT; k++) v += tb[k] * eW[(SSC + k) * CC + c];
        g_hs[n * CC + c] = v;
    }
}

// ---------------- scan (and re-zero counters) ----------------
__global__ void k_scan() {
    __shared__ int sh[1024];
    int t = threadIdx.x;
    int4 v = ((const int4*)g_cnt)[t];
    int s = v.x + v.y + v.z + v.w;
    sh[t] = s;
    __syncthreads();
    for (int off = 1; off < 1024; off <<= 1) {
        int add = (t >= off) ? sh[t - off] : 0;
        __syncthreads();
        sh[t] += add;
        __syncthreads();
    }
    int excl = (t == 0) ? 0 : sh[t - 1];
    g_off[4 * t + 0] = excl;
    g_off[4 * t + 1] = excl + v.x;
    g_off[4 * t + 2] = excl + v.x + v.y;
    g_off[4 * t + 3] = excl + v.x + v.y + v.z;
    if (t == 1023) g_off[NN] = sh[1023];
    ((int4*)g_cnt)[t] = make_int4(0, 0, 0, 0);
    ((int4*)g_cur)[t] = make_int4(0, 0, 0, 0);
}

// ---------------- edge kernel: (scatter+) Y + radial MLP as tiled GEMM ----------------
// Phase 1: 1 thread per edge — scatter slot, Y[16], h[64] (silu computed once).
// Phase 2: thread = (sub, eg) computes 4 edges x 16 outputs with fma.rn.f32x2.
#define ESM_H   (HRR * (TE + 4) * 4)                 // 66560
#define ESM_W2  (HRR * CC * 4)                       // 16384
#define ESM_TOT (ESM_H + ESM_W2 + 3 * HRR * 4 + TE * 4)

template <int LAYER>
__global__ void __launch_bounds__(256, 2) k_edge(const int* __restrict__ ei,
                                                 const float* __restrict__ pos0,
                                                 const float* __restrict__ W1,
                                                 const float* __restrict__ B1,
                                                 const float* __restrict__ W2full) {
    extern __shared__ char esm[];
    float (*sH)[TE + 4] = (float(*)[TE + 4])esm;
    float (*sW2)[CC]    = (float(*)[CC])(esm + ESM_H);
    float* sW1a = (float*)(esm + ESM_H + ESM_W2);
    float* sW1b = sW1a + HRR;
    float* sBB  = sW1b + HRR;
    int*   sP   = (int*)(sBB + HRR);

    int t = threadIdx.x;
    const float* w2 = W2full + LAYER * HRR * CC;
    {
        const float4* src = (const float4*)w2;
        float4* dst = (float4*)sW2;
        for (int i = t; i < HRR * CC / 4; i += 256) dst[i] = src[i];
        if (t < HRR) {
            sW1a[t] = W1[LAYER * 2 * HRR + t];
            sW1b[t] = W1[LAYER * 2 * HRR + HRR + t];
            sBB[t]  = B1[LAYER * HRR + t];
        }
    }
    __syncthreads();

    // -------- phase 1 --------
    int e = blockIdx.x * TE + t;
    int s, r, p;
    if (LAYER == 0) {
        s = ei[e]; r = ei[EE + e];
        p = g_off[r] + atomicAdd(&g_cur[r], 1);
        g_ss[p] = s; g_sr[p] = r;
    } else {
        s = g_ss[e]; r = g_sr[e];
        p = e;
    }
    sP[t] = p;

    float len, len0, x, y, z;
    {
        float ax = pos0[s * 3], ay = pos0[s * 3 + 1], az = pos0[s * 3 + 2];
        float bx = pos0[r * 3], by = pos0[r * 3 + 1], bz = pos0[r * 3 + 2];
        float dx = bx - ax, dy = by - ay, dz = bz - az;
        len0 = sqrtf(dx * dx + dy * dy + dz * dz);
        float vx, vy, vz;
        if (LAYER == 0) {
            vx = dx; vy = dy; vz = dz; len = len0;
        } else {
            float px = g_pos1[r * 3]     - g_pos1[s * 3];
            float py = g_pos1[r * 3 + 1] - g_pos1[s * 3 + 1];
            float pz = g_pos1[r * 3 + 2] - g_pos1[s * 3 + 2];
            vx = px; vy = py; vz = pz;
            len = sqrtf(vx * vx + vy * vy + vz * vz);
        }
        float inv = 1.0f / (len + EPSF);
        x = vx * inv; y = vy * inv; z = vz * inv;
    }

    {
        float xx = x * x, yy = y * y, zz = z * z;
        float4* yp = (float4*)&g_Y[p * 4];
        yp[0] = make_float4(1.0f,
                            1.7320508075688772f * x,
                            1.7320508075688772f * y,
                            1.7320508075688772f * z);
        yp[1] = make_float4(3.872983346207417f * x * y,
                            3.872983346207417f * y * z,
                            1.118033988749895f * (3.0f * zz - 1.0f),
                            3.872983346207417f * x * z);
        yp[2] = make_float4(1.9364916731037085f * (xx - yy),
                            2.091650066335189f * y * (3.0f * xx - yy),
                            10.246950765959598f * x * y * z,
                            1.6201851746019651f * y * (5.0f * zz - 1.0f));
        yp[3] = make_float4(1.3228756555322954f * z * (5.0f * zz - 3.0f),
                            1.6201851746019651f * x * (5.0f * zz - 1.0f),
                            5.123475382979799f * z * (xx - yy),
                            2.091650066335189f * x * (xx - 3.0f * yy));
    }

    const float invAvg = 1.0f / 32.0f;
#pragma unroll 4
    for (int j = 0; j < HRR; j++) {
        float a = fmaf(len0, sW1a[j], fmaf(len, sW1b[j], sBB[j]));
        float h = __fdividef(a, 1.0f + __expf(-a)) * invAvg;   // silu, /AVG folded
        sH[j][t] = h;
    }
    __syncthreads();

    // -------- phase 2: R tile = H @ W2 (f32x2) --------
    int sub = t & 3;
    int eg = t >> 2;
    u64 acc[4][8];
#pragma unroll
    for (int ed = 0; ed < 4; ed++)
#pragma unroll
        for (int k = 0; k < 8; k++) acc[ed][k] = 0ull;

#pragma unroll 4
    for (int j = 0; j < HRR; j++) {
        float4 h4 = *(const float4*)&sH[j][eg * 4];
        u64 h0 = dup2(h4.x), h1 = dup2(h4.y), h2 = dup2(h4.z), h3 = dup2(h4.w);
        const ulonglong2* wr = (const ulonglong2*)&sW2[j][sub * 16];
        ulonglong2 wa = wr[0], wb = wr[1], wc = wr[2], wd = wr[3];
        fma2(acc[0][0], h0, wa.x); fma2(acc[0][1], h0, wa.y);
        fma2(acc[0][2], h0, wb.x); fma2(acc[0][3], h0, wb.y);
        fma2(acc[0][4], h0, wc.x); fma2(acc[0][5], h0, wc.y);
        fma2(acc[0][6], h0, wd.x); fma2(acc[0][7], h0, wd.y);
        fma2(acc[1][0], h1, wa.x); fma2(acc[1][1], h1, wa.y);
        fma2(acc[1][2], h1, wb.x); fma2(acc[1][3], h1, wb.y);
        fma2(acc[1][4], h1, wc.x); fma2(acc[1][5], h1, wc.y);
        fma2(acc[1][6], h1, wd.x); fma2(acc[1][7], h1, wd.y);
        fma2(acc[2][0], h2, wa.x); fma2(acc[2][1], h2, wa.y);
        fma2(acc[2][2], h2, wb.x); fma2(acc[2][3], h2, wb.y);
        fma2(acc[2][4], h2, wc.x); fma2(acc[2][5], h2, wc.y);
        fma2(acc[2][6], h2, wd.x); fma2(acc[2][7], h2, wd.y);
        fma2(acc[3][0], h3, wa.x); fma2(acc[3][1], h3, wa.y);
        fma2(acc[3][2], h3, wb.x); fma2(acc[3][3], h3, wb.y);
        fma2(acc[3][4], h3, wc.x); fma2(acc[3][5], h3, wc.y);
        fma2(acc[3][6], h3, wd.x); fma2(acc[3][7], h3, wd.y);
    }

#pragma unroll
    for (int ed = 0; ed < 4; ed++) {
        int pp = sP[eg * 4 + ed];
        float o[16];
#pragma unroll
        for (int k = 0; k < 8; k++) upk2(acc[ed][k], o[2 * k], o[2 * k + 1]);
        float4* dst = (float4*)&g_R[pp * CC + sub * 16];
        dst[0] = make_float4(o[0], o[1], o[2], o[3]);
        dst[1] = make_float4(o[4], o[5], o[6], o[7]);
        dst[2] = make_float4(o[8], o[9], o[10], o[11]);
        dst[3] = make_float4(o[12], o[13], o[14], o[15]);
    }
}

// ---------------- per-node: aggregate + mix + gate + prod + pos ----------------
// 128 threads = 2 nodes x 64 channels; persistent loop over 2 node-pairs (1 wave).
template <int LAYER>
__global__ void __launch_bounds__(128) k_node(const float* __restrict__ pos_in,
                                              const float* __restrict__ pos0,
                                              const float* __restrict__ Wmix,
                                              const float* __restrict__ Wprod,
                                              const float* __restrict__ Wvec,
                                              float* __restrict__ pos_out) {
    constexpr bool LAST = (LAYER == LL - 1);
    int t = threadIdx.x;
    int ni = t >> 6;
    int d = t & 63;

    __shared__ __align__(16) float sS[2][64][16];
    __shared__ float sG[2][64];
    __shared__ float sV[2][3][64];

    for (int pair = blockIdx.x; pair < NN / 2; pair += gridDim.x) {
        int n = pair * 2 + ni;

        float acc[16];
#pragma unroll
        for (int x = 0; x < 16; x++) acc[x] = 0.f;

        int e0 = g_off[n], e1 = g_off[n + 1];
#pragma unroll 2
        for (int e = e0; e < e1; ++e) {
            int s = g_ss[e];
            float R = g_R[e * CC + d];          // already /AVG
            const float4* Yp = &g_Y[e * 4];
            float4 Ya = Yp[0], Yb = Yp[1], Yc = Yp[2], Yd = Yp[3];
            float Yv[16] = {Ya.x, Ya.y, Ya.z, Ya.w, Yb.x, Yb.y, Yb.z, Yb.w,
                            Yc.x, Yc.y, Yc.z, Yc.w, Yd.x, Yd.y, Yd.z, Yd.w};
            if (LAYER == 0) {
                float hs = g_hs[s * CC + d];
                float w = R * hs;
                acc[0] += 2.0f * w;
#pragma unroll
                for (int x = 1; x < 16; x++) acc[x] += w * Yv[x];
            } else {
                float hv[16];
#pragma unroll
                for (int x = 0; x < 16; x++) hv[x] = g_nf[(s * SHH + x) * CC + d];
                float w = R * hv[0];
                float tp = 0.f;
#pragma unroll
                for (int x = 0; x < 16; x++) tp += hv[x] * Yv[x];
                acc[0] += w + R * tp;
#pragma unroll
                for (int x = 1; x < 16; x++) acc[x] += w * Yv[x];
            }
        }

        float4* st = (float4*)&sS[ni][d][0];
        st[0] = make_float4(acc[0], acc[1], acc[2], acc[3]);
        st[1] = make_float4(acc[4], acc[5], acc[6], acc[7]);
        st[2] = make_float4(acc[8], acc[9], acc[10], acc[11]);
        st[3] = make_float4(acc[12], acc[13], acc[14], acc[15]);
        __syncthreads();

        // mixing (f32x2): mixed[d][x] = sum_cc agg[cc][x] * Wmix[l][ib(x)][cc][d]
        u64 m2[8];
#pragma unroll
        for (int k = 0; k < 8; k++) m2[k] = 0ull;
        const float* Wm = Wmix + LAYER * 4 * CC * CC + d;
#pragma unroll 4
        for (int cc = 0; cc < CC; cc++) {
            float w0 = Wm[(0 * CC + cc) * CC];
            float w1 = Wm[(1 * CC + cc) * CC];
            float w2 = Wm[(2 * CC + cc) * CC];
            float w3 = Wm[(3 * CC + cc) * CC];
            const ulonglong2* ap = (const ulonglong2*)&sS[ni][cc][0];
            ulonglong2 A = ap[0], B = ap[1], Cq = ap[2], D = ap[3];
            u64 W01 = pk2(w0, w1), W11 = dup2(w1), W22 = dup2(w2);
            u64 W23 = pk2(w2, w3), W33 = dup2(w3);
            fma2(m2[0], A.x, W01);   // x0,x1
            fma2(m2[1], A.y, W11);   // x2,x3
            fma2(m2[2], B.x, W22);   // x4,x5
            fma2(m2[3], B.y, W22);   // x6,x7
            fma2(m2[4], Cq.x, W23);  // x8,x9
            fma2(m2[5], Cq.y, W33);  // x10,x11
            fma2(m2[6], D.x, W33);   // x12,x13
            fma2(m2[7], D.y, W33);   // x14,x15
        }
        __syncthreads();  // done reading agg

        // stage mixed + gate
        ulonglong2* st2 = (ulonglong2*)&sS[ni][d][0];
        ulonglong2 t01; t01.x = m2[0]; t01.y = m2[1]; st2[0] = t01;
        ulonglong2 t23; t23.x = m2[2]; t23.y = m2[3]; st2[1] = t23;
        ulonglong2 t45; t45.x = m2[4]; t45.y = m2[5]; st2[2] = t45;
        ulonglong2 t67; t67.x = m2[6]; t67.y = m2[7]; st2[3] = t67;
        float s0, s1;
        upk2(m2[0], s0, s1);
        sG[ni][d] = s0 * (1.0f + s0 + s0 * s0);
        __syncthreads();

        // prod (f32x2): nf = mixed + (mixed*gate) @ Wprod
        u64 p2[8];
#pragma unroll
        for (int k = 0; k < 8; k++) p2[k] = 0ull;
        const float* Wp = Wprod + LAYER * CC * CC + d;
#pragma unroll 4
        for (int cc = 0; cc < CC; cc++) {
            float wg = Wp[cc * CC] * sG[ni][cc];
            u64 wg2 = dup2(wg);
            const ulonglong2* ap = (const ulonglong2*)&sS[ni][cc][0];
            ulonglong2 A = ap[0], B = ap[1], Cq = ap[2], D = ap[3];
            fma2(p2[0], A.x, wg2);  fma2(p2[1], A.y, wg2);
            fma2(p2[2], B.x, wg2);  fma2(p2[3], B.y, wg2);
            fma2(p2[4], Cq.x, wg2); fma2(p2[5], Cq.y, wg2);
            fma2(p2[6], D.x, wg2);  fma2(p2[7], D.y, wg2);
        }
        float nf[16];
#pragma unroll
        for (int k = 0; k < 8; k++) {
            u64 v = add2(m2[k], p2[k]);
            upk2(v, nf[2 * k], nf[2 * k + 1]);
        }

        if (!LAST) {
#pragma unroll
            for (int x = 0; x < 16; x++) g_nf[(n * SHH + x) * CC + d] = nf[x];
        }

        float wv = Wvec[d];
        sV[ni][0][d] = nf[1] * wv;
        sV[ni][1][d] = nf[2] * wv;
        sV[ni][2][d] = nf[3] * wv;
        __syncthreads();
        if (d < 3) {
            float sum = 0.f;
#pragma unroll 8
            for (int dd = 0; dd < CC; dd++) sum += sV[ni][d][dd];
            float pp = pos_in[n * 3 + d] + sum;
            pos_out[n * 3 + d] = LAST ? (pp - pos0[n * 3 + d]) : pp;
        }
        __syncthreads();  // protect smem before next pair iteration
    }
}

// ---------------- launch ----------------
extern "C" void kernel_launch(void* const* d_in, const int* in_sizes, int n_in,
                              void* d_out, int out_size) {
    const float* positions = (const float*)d_in[0];
    const int*   node_attrs = (const int*)d_in[1];
    const float* time_emb = (const float*)d_in[2];
    const int*   edge_index = (const int*)d_in[3];
    const float* embed_W = (const float*)d_in[4];
    const float* embed_b = (const float*)d_in[5];
    const float* radial_W1 = (const float*)d_in[6];
    const float* radial_b1 = (const float*)d_in[7];
    const float* radial_W2 = (const float*)d_in[8];
    const float* Wmix = (const float*)d_in[9];
    const float* Wprod = (const float*)d_in[10];
    const float* Wvec = (const float*)d_in[11];
    float* out = (float*)d_out;

    float* g_pos1_p = nullptr;
    cudaGetSymbolAddress((void**)&g_pos1_p, g_pos1);

    cudaFuncSetAttribute(k_edge<0>, cudaFuncAttributeMaxDynamicSharedMemorySize, ESM_TOT);
    cudaFuncSetAttribute(k_edge<1>, cudaFuncAttributeMaxDynamicSharedMemorySize, ESM_TOT);

    k_hist_prep<<<512 + 1024, 256>>>(edge_index, node_attrs, time_emb, embed_W, embed_b);
    k_scan<<<1, 1024>>>();
    k_edge<0><<<EE / TE, 256, ESM_TOT>>>(edge_index, positions, radial_W1, radial_b1, radial_W2);
    k_node<0><<<1024, 128>>>(positions, positions, Wmix, Wprod, Wvec + 0 * CC, g_pos1_p);
    k_edge<1><<<EE / TE, 256, ESM_TOT>>>(edge_index, positions, radial_W1, radial_b1, radial_W2);
    k_node<1><<<1024, 128>>>(g_pos1_p, positions, Wmix, Wprod, Wvec + 1 * CC, out);
}

// round 5
// speedup vs baseline: 3.6036x; 1.0309x over previous
#include <cuda_runtime.h>
#include <math.h>

#define NN 4096
#define EE 131072
#define CC 64
#define TT 32
#define SSC 5
#define LL 2
#define HRR 64
#define SHH 16
#define EPSF 1e-9f
#define TE 256

typedef unsigned long long u64;

__device__ __forceinline__ u64 pk2(float a, float b) {
    u64 r; asm("mov.b64 %0,{%1,%2};" : "=l"(r) : "f"(a), "f"(b)); return r;
}
__device__ __forceinline__ u64 dup2(float a) { return pk2(a, a); }
__device__ __forceinline__ void upk2(u64 v, float& a, float& b) {
    asm("mov.b64 {%0,%1},%2;" : "=f"(a), "=f"(b) : "l"(v));
}
__device__ __forceinline__ void fma2(u64& d, u64 a, u64 b) {
    asm("fma.rn.f32x2 %0,%1,%2,%0;" : "+l"(d) : "l"(a), "l"(b));
}
__device__ __forceinline__ u64 add2(u64 a, u64 b) {
    u64 r; asm("add.rn.f32x2 %0,%1,%2;" : "=l"(r) : "l"(a), "l"(b)); return r;
}

// ---------------- device scratch (static, zero-initialized at load) ----------------
__device__ int    g_cnt[NN];
__device__ int    g_cur[NN];
__device__ int    g_off[NN + 1];
__device__ int    g_ss[EE];            // sorted send
__device__ int    g_sr[EE];            // sorted recv
__device__ float  g_hs[NN * CC];       // layer-0 node scalars
__device__ float  g_nf[NN * SHH * CC]; // node feats after layer 0, [n][x][c]
__device__ float4 g_Y[EE * 4];         // Y per sorted edge: [e*4 + g]
__device__ float  g_R[EE * CC];        // R per sorted edge (already /AVG): [e*CC + c]
__device__ float  g_pos1[NN * 3];      // positions after layer 0

// ---------------- fused: histogram + node embedding ----------------
__global__ void k_hist_prep(const int* __restrict__ ei,
                            const int* __restrict__ attrs,
                            const float* __restrict__ timeE,
                            const float* __restrict__ eW,
                            const float* __restrict__ eB) {
    int b = blockIdx.x;
    int t = threadIdx.x;
    if (b < 512) {
        int e = b * 256 + t;
        atomicAdd(&g_cnt[ei[EE + e]], 1);
    } else {
        int n = (b - 512) * 4 + (t >> 6);
        int c = t & 63;
        int a = attrs[n] - 1;
        float v = eB[c] + eW[a * CC + c];
        const float* tb = timeE + n * TT;
#pragma unroll
        for (int k = 0; k < TT; k++) v += tb[k] * eW[(SSC + k) * CC + c];
        g_hs[n * CC + c] = v;
    }
}

// ---------------- scan (and re-zero counters) ----------------
__global__ void k_scan() {
    __shared__ int sh[1024];
    int t = threadIdx.x;
    int4 v = ((const int4*)g_cnt)[t];
    int s = v.x + v.y + v.z + v.w;
    sh[t] = s;
    __syncthreads();
    for (int off = 1; off < 1024; off <<= 1) {
        int add = (t >= off) ? sh[t - off] : 0;
        __syncthreads();
        sh[t] += add;
        __syncthreads();
    }
    int excl = (t == 0) ? 0 : sh[t - 1];
    g_off[4 * t + 0] = excl;
    g_off[4 * t + 1] = excl + v.x;
    g_off[4 * t + 2] = excl + v.x + v.y;
    g_off[4 * t + 3] = excl + v.x + v.y + v.z;
    if (t == 1023) g_off[NN] = sh[1023];
    ((int4*)g_cnt)[t] = make_int4(0, 0, 0, 0);
    ((int4*)g_cur)[t] = make_int4(0, 0, 0, 0);
}

// ---------------- edge kernel ----------------
// 512 threads per block, TE=256 edges. Phase 1 (t<256): scatter + Y + (len0,len).
// Then 2 chunks of 32 hidden units: fill sH, then all 512 threads accumulate
// R tile (thread = 2 edges x 16 outputs) with fma.rn.f32x2.
#define ESM_H   (32 * 260 * 4)        // 33280
#define ESM_W   (HRR * 40 * 8)        // 20480 (padded u64 rows: 4 subs x (8+2) u64)
#define ESM_MISC (3 * HRR * 4 + TE * 4)
#define ESM_TOT (ESM_H + ESM_W + ESM_MISC)

template <int LAYER>
__global__ void __launch_bounds__(512) k_edge(const int* __restrict__ ei,
                                              const float* __restrict__ pos0,
                                              const float* __restrict__ W1,
                                              const float* __restrict__ B1,
                                              const float* __restrict__ W2full) {
    extern __shared__ char esm[];
    float (*sH)[260] = (float(*)[260])esm;
    u64*   sW2v = (u64*)(esm + ESM_H);
    float* sW1a = (float*)(esm + ESM_H + ESM_W);
    float* sW1b = sW1a + HRR;
    float* sBB  = sW1b + HRR;
    int*   sP   = (int*)(sBB + HRR);

    int t = threadIdx.x;
    const float* w2 = W2full + LAYER * HRR * CC;
    for (int idx = t; idx < HRR * 32; idx += 512) {
        int j = idx >> 5, q = idx & 31;
        int sub = q >> 3, k = q & 7;
        sW2v[j * 40 + sub * 10 + k] = ((const u64*)(w2 + j * CC))[q];
    }
    if (t < HRR) {
        sW1a[t] = W1[LAYER * 2 * HRR + t];
        sW1b[t] = W1[LAYER * 2 * HRR + HRR + t];
        sBB[t]  = B1[LAYER * HRR + t];
    }

    float len = 0.f, len0 = 0.f;
    if (t < TE) {
        int e = blockIdx.x * TE + t;
        int s, r, p;
        if (LAYER == 0) {
            s = ei[e]; r = ei[EE + e];
            p = g_off[r] + atomicAdd(&g_cur[r], 1);
            g_ss[p] = s; g_sr[p] = r;
        } else {
            s = g_ss[e]; r = g_sr[e];
            p = e;
        }
        sP[t] = p;

        float ax = pos0[s * 3], ay = pos0[s * 3 + 1], az = pos0[s * 3 + 2];
        float bx = pos0[r * 3], by = pos0[r * 3 + 1], bz = pos0[r * 3 + 2];
        float dx = bx - ax, dy = by - ay, dz = bz - az;
        len0 = sqrtf(dx * dx + dy * dy + dz * dz);
        float vx, vy, vz;
        if (LAYER == 0) {
            vx = dx; vy = dy; vz = dz; len = len0;
        } else {
            vx = g_pos1[r * 3]     - g_pos1[s * 3];
            vy = g_pos1[r * 3 + 1] - g_pos1[s * 3 + 1];
            vz = g_pos1[r * 3 + 2] - g_pos1[s * 3 + 2];
            len = sqrtf(vx * vx + vy * vy + vz * vz);
        }
        float inv = 1.0f / (len + EPSF);
        float x = vx * inv, y = vy * inv, z = vz * inv;
        float xx = x * x, yy = y * y, zz = z * z;
        float4* yp = (float4*)&g_Y[p * 4];
        yp[0] = make_float4(1.0f,
                            1.7320508075688772f * x,
                            1.7320508075688772f * y,
                            1.7320508075688772f * z);
        yp[1] = make_float4(3.872983346207417f * x * y,
                            3.872983346207417f * y * z,
                            1.118033988749895f * (3.0f * zz - 1.0f),
                            3.872983346207417f * x * z);
        yp[2] = make_float4(1.9364916731037085f * (xx - yy),
                            2.091650066335189f * y * (3.0f * xx - yy),
                            10.246950765959598f * x * y * z,
                            1.6201851746019651f * y * (5.0f * zz - 1.0f));
        yp[3] = make_float4(1.3228756555322954f * z * (5.0f * zz - 3.0f),
                            1.6201851746019651f * x * (5.0f * zz - 1.0f),
                            5.123475382979799f * z * (xx - yy),
                            2.091650066335189f * x * (xx - 3.0f * yy));
    }
    __syncthreads();

    int sub = t & 3;       // which 16 of the 64 outputs
    int eg  = t >> 2;      // edge pair index 0..127
    u64 acc[2][8];
#pragma unroll
    for (int ed = 0; ed < 2; ed++)
#pragma unroll
        for (int k = 0; k < 8; k++) acc[ed][k] = 0ull;

    const float invAvg = 1.0f / 32.0f;
#pragma unroll
    for (int chunk = 0; chunk < 2; chunk++) {
        if (t < TE) {
#pragma unroll
            for (int jj = 0; jj < 32; jj++) {
                int j = chunk * 32 + jj;
                float a = fmaf(len0, sW1a[j], fmaf(len, sW1b[j], sBB[j]));
                sH[jj][t] = __fdividef(a, 1.0f + __expf(-a)) * invAvg;
            }
        }
        __syncthreads();
#pragma unroll 4
        for (int jj = 0; jj < 32; jj++) {
            int j = chunk * 32 + jj;
            float2 h2 = *(const float2*)&sH[jj][eg * 2];
            u64 hd0 = dup2(h2.x), hd1 = dup2(h2.y);
            const ulonglong2* wr = (const ulonglong2*)&sW2v[j * 40 + sub * 10];
            ulonglong2 wA = wr[0], wB = wr[1], wC = wr[2], wD = wr[3];
            fma2(acc[0][0], hd0, wA.x); fma2(acc[0][1], hd0, wA.y);
            fma2(acc[0][2], hd0, wB.x); fma2(acc[0][3], hd0, wB.y);
            fma2(acc[0][4], hd0, wC.x); fma2(acc[0][5], hd0, wC.y);
            fma2(acc[0][6], hd0, wD.x); fma2(acc[0][7], hd0, wD.y);
            fma2(acc[1][0], hd1, wA.x); fma2(acc[1][1], hd1, wA.y);
            fma2(acc[1][2], hd1, wB.x); fma2(acc[1][3], hd1, wB.y);
            fma2(acc[1][4], hd1, wC.x); fma2(acc[1][5], hd1, wC.y);
            fma2(acc[1][6], hd1, wD.x); fma2(acc[1][7], hd1, wD.y);
        }
        __syncthreads();
    }

#pragma unroll
    for (int ed = 0; ed < 2; ed++) {
        int p = sP[eg * 2 + ed];
        ulonglong2* dst = (ulonglong2*)&g_R[p * CC + sub * 16];
        ulonglong2 v0; v0.x = acc[ed][0]; v0.y = acc[ed][1];
        ulonglong2 v1; v1.x = acc[ed][2]; v1.y = acc[ed][3];
        ulonglong2 v2; v2.x = acc[ed][4]; v2.y = acc[ed][5];
        ulonglong2 v3; v3.x = acc[ed][6]; v3.y = acc[ed][7];
        dst[0] = v0; dst[1] = v1; dst[2] = v2; dst[3] = v3;
    }
}

// ---------------- per-node: aggregate + mix + gate + prod + pos ----------------
// Block = 128 threads (2 node-slots x 64 channels) handles 4 nodes.
// GEMV phases: each thread serves 2 nodes off one weight load (amortized).
template <int LAYER>
__global__ void __launch_bounds__(128, 6) k_node(const float* __restrict__ pos_in,
                                                 const float* __restrict__ pos0,
                                                 const float* __restrict__ Wmix,
                                                 const float* __restrict__ Wprod,
                                                 const float* __restrict__ Wvec,
                                                 float* __restrict__ pos_out) {
    constexpr bool LAST = (LAYER == LL - 1);
    int t = threadIdx.x;
    int sl = t >> 6;
    int d = t & 63;
    int base = blockIdx.x * 4;

    __shared__ __align__(16) float sS[4][64][16];
    __shared__ float sG[4][64];
    __shared__ float sV[4][3][64];

    // ---- aggregation: 2 rounds fill 4 tiles ----
#pragma unroll
    for (int k = 0; k < 2; k++) {
        int g = 2 * k + sl;
        int n = base + g;
        u64 a2[8];
#pragma unroll
        for (int q = 0; q < 8; q++) a2[q] = 0ull;
        float extra = 0.f;

        int e0 = g_off[n], e1 = g_off[n + 1];
#pragma unroll 2
        for (int e = e0; e < e1; ++e) {
            int s = g_ss[e];
            float R = g_R[e * CC + d];          // already /AVG
            const ulonglong2* up = (const ulonglong2*)&g_Y[e * 4];
            ulonglong2 U0 = up[0], U1 = up[1], U2 = up[2], U3 = up[3];
            float w;
            if (LAYER == 0) {
                float hs = g_hs[s * CC + d];
                w = R * hs;
                extra += w;                      // tp term (Y0=1)
            } else {
                float hv[16];
#pragma unroll
                for (int x = 0; x < 16; x++) hv[x] = g_nf[(s * SHH + x) * CC + d];
                u64 tp2 = 0ull;
                fma2(tp2, pk2(hv[0], hv[1]),  U0.x);
                fma2(tp2, pk2(hv[2], hv[3]),  U0.y);
                fma2(tp2, pk2(hv[4], hv[5]),  U1.x);
                fma2(tp2, pk2(hv[6], hv[7]),  U1.y);
                fma2(tp2, pk2(hv[8], hv[9]),  U2.x);
                fma2(tp2, pk2(hv[10], hv[11]), U2.y);
                fma2(tp2, pk2(hv[12], hv[13]), U3.x);
                fma2(tp2, pk2(hv[14], hv[15]), U3.y);
                float tlo, thi; upk2(tp2, tlo, thi);
                w = R * hv[0];
                extra = fmaf(R, tlo + thi, extra);
            }
            u64 wd = dup2(w);
            fma2(a2[0], wd, U0.x); fma2(a2[1], wd, U0.y);
            fma2(a2[2], wd, U1.x); fma2(a2[3], wd, U1.y);
            fma2(a2[4], wd, U2.x); fma2(a2[5], wd, U2.y);
            fma2(a2[6], wd, U3.x); fma2(a2[7], wd, U3.y);
        }
        float av[16];
#pragma unroll
        for (int q = 0; q < 8; q++) upk2(a2[q], av[2 * q], av[2 * q + 1]);
        av[0] += extra;
        float4* st = (float4*)&sS[g][d][0];
        st[0] = make_float4(av[0], av[1], av[2], av[3]);
        st[1] = make_float4(av[4], av[5], av[6], av[7]);
        st[2] = make_float4(av[8], av[9], av[10], av[11]);
        st[3] = make_float4(av[12], av[13], av[14], av[15]);
    }
    __syncthreads();

    int gA = sl, gB = sl + 2;

    // ---- mix: 2 nodes per thread, weights loaded/packed once ----
    u64 mA[8], mB[8];
#pragma unroll
    for (int q = 0; q < 8; q++) { mA[q] = 0ull; mB[q] = 0ull; }
    const float* Wm = Wmix + LAYER * 4 * CC * CC + d;
#pragma unroll 4
    for (int cc = 0; cc < CC; cc++) {
        float w0 = Wm[(0 * CC + cc) * CC];
        float w1 = Wm[(1 * CC + cc) * CC];
        float w2 = Wm[(2 * CC + cc) * CC];
        float w3 = Wm[(3 * CC + cc) * CC];
        u64 W01 = pk2(w0, w1), W11 = dup2(w1), W22 = dup2(w2);
        u64 W23 = pk2(w2, w3), W33 = dup2(w3);
        {
            const ulonglong2* ap = (const ulonglong2*)&sS[gA][cc][0];
            ulonglong2 A = ap[0], B = ap[1], Cq = ap[2], D = ap[3];
            fma2(mA[0], A.x, W01);  fma2(mA[1], A.y, W11);
            fma2(mA[2], B.x, W22);  fma2(mA[3], B.y, W22);
            fma2(mA[4], Cq.x, W23); fma2(mA[5], Cq.y, W33);
            fma2(mA[6], D.x, W33);  fma2(mA[7], D.y, W33);
        }
        {
            const ulonglong2* ap = (const ulonglong2*)&sS[gB][cc][0];
            ulonglong2 A = ap[0], B = ap[1], Cq = ap[2], D = ap[3];
            fma2(mB[0], A.x, W01);  fma2(mB[1], A.y, W11);
            fma2(mB[2], B.x, W22);  fma2(mB[3], B.y, W22);
            fma2(mB[4], Cq.x, W23); fma2(mB[5], Cq.y, W33);
            fma2(mB[6], D.x, W33);  fma2(mB[7], D.y, W33);
        }
    }
    __syncthreads();  // agg reads done

    // ---- stage mixed tiles + gates (registers released after this) ----
    {
        ulonglong2* st2 = (ulonglong2*)&sS[gA][d][0];
        ulonglong2 v0; v0.x = mA[0]; v0.y = mA[1]; st2[0] = v0;
        ulonglong2 v1; v1.x = mA[2]; v1.y = mA[3]; st2[1] = v1;
        ulonglong2 v2; v2.x = mA[4]; v2.y = mA[5]; st2[2] = v2;
        ulonglong2 v3; v3.x = mA[6]; v3.y = mA[7]; st2[3] = v3;
        float s0, s1; upk2(mA[0], s0, s1);
        sG[gA][d] = s0 * (1.0f + s0 + s0 * s0);
    }
    {
        ulonglong2* st2 = (ulonglong2*)&sS[gB][d][0];
        ulonglong2 v0; v0.x = mB[0]; v0.y = mB[1]; st2[0] = v0;
        ulonglong2 v1; v1.x = mB[2]; v1.y = mB[3]; st2[1] = v1;
        ulonglong2 v2; v2.x = mB[4]; v2.y = mB[5]; st2[2] = v2;
        ulonglong2 v3; v3.x = mB[6]; v3.y = mB[7]; st2[3] = v3;
        float s0, s1; upk2(mB[0], s0, s1);
        sG[gB][d] = s0 * (1.0f + s0 + s0 * s0);
    }
    __syncthreads();

    // ---- prod: gate folded into weight ----
    u64 pA[8], pB[8];
#pragma unroll
    for (int q = 0; q < 8; q++) { pA[q] = 0ull; pB[q] = 0ull; }
    const float* Wp = Wprod + LAYER * CC * CC + d;
#pragma unroll 4
    for (int cc = 0; cc < CC; cc++) {
        float w = Wp[cc * CC];
        u64 wgA = dup2(w * sG[gA][cc]);
        u64 wgB = dup2(w * sG[gB][cc]);
        {
            const ulonglong2* ap = (const ulonglong2*)&sS[gA][cc][0];
            ulonglong2 A = ap[0], B = ap[1], Cq = ap[2], D = ap[3];
            fma2(pA[0], A.x, wgA);  fma2(pA[1], A.y, wgA);
            fma2(pA[2], B.x, wgA);  fma2(pA[3], B.y, wgA);
            fma2(pA[4], Cq.x, wgA); fma2(pA[5], Cq.y, wgA);
            fma2(pA[6], D.x, wgA);  fma2(pA[7], D.y, wgA);
        }
        {
            const ulonglong2* ap = (const ulonglong2*)&sS[gB][cc][0];
            ulonglong2 A = ap[0], B = ap[1], Cq = ap[2], D = ap[3];
            fma2(pB[0], A.x, wgB);  fma2(pB[1], A.y, wgB);
            fma2(pB[2], B.x, wgB);  fma2(pB[3], B.y, wgB);
            fma2(pB[4], Cq.x, wgB); fma2(pB[5], Cq.y, wgB);
            fma2(pB[6], D.x, wgB);  fma2(pB[7], D.y, wgB);
        }
    }

    // ---- nf = mixed (reload) + prod ----
    float nfA[16], nfB[16];
    {
        const ulonglong2* ap = (const ulonglong2*)&sS[gA][d][0];
        ulonglong2 A = ap[0], B = ap[1], Cq = ap[2], D = ap[3];
        upk2(add2(A.x, pA[0]), nfA[0], nfA[1]);
        upk2(add2(A.y, pA[1]), nfA[2], nfA[3]);
        upk2(add2(B.x, pA[2]), nfA[4], nfA[5]);
        upk2(add2(B.y, pA[3]), nfA[6], nfA[7]);
        upk2(add2(Cq.x, pA[4]), nfA[8], nfA[9]);
        upk2(add2(Cq.y, pA[5]), nfA[10], nfA[11]);
        upk2(add2(D.x, pA[6]), nfA[12], nfA[13]);
        upk2(add2(D.y, pA[7]), nfA[14], nfA[15]);
    }
    {
        const ulonglong2* ap = (const ulonglong2*)&sS[gB][d][0];
        ulonglong2 A = ap[0], B = ap[1], Cq = ap[2], D = ap[3];
        upk2(add2(A.x, pB[0]), nfB[0], nfB[1]);
        upk2(add2(A.y, pB[1]), nfB[2], nfB[3]);
        upk2(add2(B.x, pB[2]), nfB[4], nfB[5]);
        upk2(add2(B.y, pB[3]), nfB[6], nfB[7]);
        upk2(add2(Cq.x, pB[4]), nfB[8], nfB[9]);
        upk2(add2(Cq.y, pB[5]), nfB[10], nfB[11]);
        upk2(add2(D.x, pB[6]), nfB[12], nfB[13]);
        upk2(add2(D.y, pB[7]), nfB[14], nfB[15]);
    }

    int nA = base + gA, nB = base + gB;
    if (!LAST) {
#pragma unroll
        for (int x = 0; x < 16; x++) g_nf[(nA * SHH + x) * CC + d] = nfA[x];
#pragma unroll
        for (int x = 0; x < 16; x++) g_nf[(nB * SHH + x) * CC + d] = nfB[x];
    }

    float wv = Wvec[d];
    sV[gA][0][d] = nfA[1] * wv;
    sV[gA][1][d] = nfA[2] * wv;
    sV[gA][2][d] = nfA[3] * wv;
    sV[gB][0][d] = nfB[1] * wv;
    sV[gB][1][d] = nfB[2] * wv;
    sV[gB][2][d] = nfB[3] * wv;
    __syncthreads();

    if (t < 12) {
        int g = t / 3, j = t % 3;
        float sum = 0.f;
#pragma unroll 8
        for (int dd = 0; dd < CC; dd++) sum += sV[g][j][dd];
        int n = base + g;
        float pp = pos_in[n * 3 + j] + sum;
        pos_out[n * 3 + j] = LAST ? (pp - pos0[n * 3 + j]) : pp;
    }
}

// ---------------- launch ----------------
extern "C" void kernel_launch(void* const* d_in, const int* in_sizes, int n_in,
                              void* d_out, int out_size) {
    const float* positions = (const float*)d_in[0];
    const int*   node_attrs = (const int*)d_in[1];
    const float* time_emb = (const float*)d_in[2];
    const int*   edge_index = (const int*)d_in[3];
    const float* embed_W = (const float*)d_in[4];
    const float* embed_b = (const float*)d_in[5];
    const float* radial_W1 = (const float*)d_in[6];
    const float* radial_b1 = (const float*)d_in[7];
    const float* radial_W2 = (const float*)d_in[8];
    const float* Wmix = (const float*)d_in[9];
    const float* Wprod = (const float*)d_in[10];
    const float* Wvec = (const float*)d_in[11];
    float* out = (float*)d_out;

    float* g_pos1_p = nullptr;
    cudaGetSymbolAddress((void**)&g_pos1_p, g_pos1);

    cudaFuncSetAttribute(k_edge<0>, cudaFuncAttributeMaxDynamicSharedMemorySize, ESM_TOT);
    cudaFuncSetAttribute(k_edge<1>, cudaFuncAttributeMaxDynamicSharedMemorySize, ESM_TOT);

    k_hist_prep<<<512 + 1024, 256>>>(edge_index, node_attrs, time_emb, embed_W, embed_b);
    k_scan<<<1, 1024>>>();
    k_edge<0><<<EE / TE, 512, ESM_TOT>>>(edge_index, positions, radial_W1, radial_b1, radial_W2);
    k_node<0><<<NN / 4, 128>>>(positions, positions, Wmix, Wprod, Wvec + 0 * CC, g_pos1_p);
    k_edge<1><<<EE / TE, 512, ESM_TOT>>>(edge_index, positions, radial_W1, radial_b1, radial_W2);
    k_node<1><<<NN / 4, 128>>>(g_pos1_p, positions, Wmix, Wprod, Wvec + 1 * CC, out);
}